// round 8
// baseline (speedup 1.0000x reference)
#include <cuda_runtime.h>
#include <math.h>

// Shapes: B=2, S=8192 -> R=16384 rows; H=2048 (=512 float4); P=512; 3P=1536; 64 slots
#define GRID     148
#define TPB      1024
#define R_ROWS   16384
#define H_DIM    2048
#define H4       512
#define P_DIM    512
#define G_DIM    1536
#define N_SLOTS  64

// Phase-A split: blocks [0,128) reduce 118 rows each; blocks [128,148) reduce 64
// rows each AND do the small matvecs.  128*118 + 20*64 = 16384.
#define RED_BLKS   128
#define ROWS_BIG   118
#define ROWS_SMALL 64

// Output layout (fp32, concatenated)
#define OFF_SURPRISE 0
#define OFF_ERR      1
#define OFF_PRED     2049
#define OFF_MEM      4097
#define OFF_STR      135169
#define OFF_PSTATE   135233

// Device scratch
__device__ __align__(16) float4 g_part[GRID * H4];   // per-block reduce partials
__device__ __align__(16) float  g_actual[H_DIM];
__device__ __align__(16) float  g_predicted[H_DIM];
__device__ __align__(16) float  g_xgru[H_DIM];
__device__ __align__(16) float  g_gi[G_DIM];
__device__ __align__(16) float  g_gh[G_DIM];
__device__ float    g_sumsq;
__device__ unsigned g_count   = 0;
__device__ unsigned g_release = 0;

__device__ __forceinline__ float warp_sum(float v) {
#pragma unroll
    for (int o = 16; o > 0; o >>= 1) v += __shfl_xor_sync(0xFFFFFFFFu, v, o);
    return v;
}
__device__ __forceinline__ float sigmoidf_(float x) { return 1.0f / (1.0f + expf(-x)); }

// Statically-unrolled streaming row sum: HN rows, stride H4 float4s.
// Full static unroll -> deep LDG pipeline (MLP >= 16).
template<int HN>
__device__ __forceinline__ float4 sum_rows(const float4* __restrict__ p) {
    float4 a0 = make_float4(0.f,0.f,0.f,0.f), a1 = a0, a2 = a0, a3 = a0;
    constexpr int HN4 = (HN / 4) * 4;
#pragma unroll
    for (int k = 0; k < HN4; k += 4) {
        float4 v0 = __ldcs(p + (size_t)(k + 0) * H4);
        float4 v1 = __ldcs(p + (size_t)(k + 1) * H4);
        float4 v2 = __ldcs(p + (size_t)(k + 2) * H4);
        float4 v3 = __ldcs(p + (size_t)(k + 3) * H4);
        a0.x += v0.x; a0.y += v0.y; a0.z += v0.z; a0.w += v0.w;
        a1.x += v1.x; a1.y += v1.y; a1.z += v1.z; a1.w += v1.w;
        a2.x += v2.x; a2.y += v2.y; a2.z += v2.z; a2.w += v2.w;
        a3.x += v3.x; a3.y += v3.y; a3.z += v3.z; a3.w += v3.w;
    }
#pragma unroll
    for (int k = HN4; k < HN; k++) {
        float4 v0 = __ldcs(p + (size_t)k * H4);
        a0.x += v0.x; a0.y += v0.y; a0.z += v0.z; a0.w += v0.w;
    }
    float4 a;
    a.x = (a0.x + a1.x) + (a2.x + a3.x);
    a.y = (a0.y + a1.y) + (a2.y + a3.y);
    a.z = (a0.z + a1.z) + (a2.z + a3.z);
    a.w = (a0.w + a1.w) + (a2.w + a3.w);
    return a;
}

// Grid barrier, monotonic release values (1,2,3). All 148 blocks co-resident
// (1 block/SM via __launch_bounds__(1024,1)). State reset at end of phase E.
__device__ __forceinline__ void grid_bar(unsigned expect) {
    __syncthreads();
    if (threadIdx.x == 0) {
        __threadfence();
        if (atomicAdd(&g_count, 1u) == GRID - 1) {
            atomicExch(&g_count, 0u);
            __threadfence();
            atomicExch(&g_release, expect);
        } else {
            while (*(volatile unsigned*)&g_release < expect) __nanosleep(32);
        }
        __threadfence();
    }
    __syncthreads();
}

__global__ void __launch_bounds__(TPB, 1)
k_fused(const float4* __restrict__ hs,       // hidden_states (16384 x 512 float4)
        const float*  __restrict__ pstate,   // (512,)
        const float4* __restrict__ mem4,     // mem_states (64 x 512 float4)
        const float*  __restrict__ strength, // (64,)
        const float*  __restrict__ Wih,      // (1536,2048)
        const float*  __restrict__ Whh,      // (1536,512)
        const float*  __restrict__ bih,
        const float*  __restrict__ bhh,
        const float*  __restrict__ ppw,      // (2048,512)
        const float*  __restrict__ ipw,      // (2048,2048)
        const float*  __restrict__ scale,
        const int*    __restrict__ wptr,
        float* __restrict__ out) {
    __shared__ float4 shv[H4];      // 8KB staging
    __shared__ float4 sfin[16];
    __shared__ bool   s_last;

    const int b = blockIdx.x, t = threadIdx.x;
    const int lane = t & 31, w = t >> 5;

    // ===================== Phase A: reduce (+aux on blocks 128..147) ========
    {
        const int c = t & 511;            // float4 column
        const int half = t >> 9;          // 0/1
        float4 a;
        if (b < RED_BLKS) {
            const float4* p = hs + (size_t)(b * ROWS_BIG + half * (ROWS_BIG / 2)) * H4 + c;
            a = sum_rows<ROWS_BIG / 2>(p);                 // 59 rows, static
        } else {
            int row0 = RED_BLKS * ROWS_BIG + (b - RED_BLKS) * ROWS_SMALL;
            const float4* p = hs + (size_t)(row0 + half * (ROWS_SMALL / 2)) * H4 + c;
            a = sum_rows<ROWS_SMALL / 2>(p);               // 32 rows, static
        }
        if (half) shv[c] = a;
        __syncthreads();
        if (!half) {
            float4 o = shv[c];
            a.x += o.x; a.y += o.y; a.z += o.z; a.w += o.w;
            g_part[b * H4 + c] = a;
        }
    }

    if (b >= RED_BLKS) {
        const float4* s4 = reinterpret_cast<const float4*>(pstate);
        if (b < 140) {
            // predicted = ppw @ pstate : 2048 rows over 12 blocks (384 warps)
            int ws = (b - 128) * 32 + w;
            for (int row = ws; row < H_DIM; row += 384) {
                const float4* wr = reinterpret_cast<const float4*>(ppw + (size_t)row * P_DIM);
                float acc = 0.f;
#pragma unroll
                for (int j = 0; j < 4; j++) {
                    float4 wv = wr[lane + 32 * j];
                    float4 xv = __ldg(s4 + lane + 32 * j);
                    acc += wv.x * xv.x + wv.y * xv.y + wv.z * xv.z + wv.w * xv.w;
                }
                acc = warp_sum(acc);
                if (lane == 0) { g_predicted[row] = acc; out[OFF_PRED + row] = acc; }
            }
        } else if (b < 147) {
            // gh = Whh @ pstate + bhh : 1536 rows over 7 blocks (224 warps)
            int ws = (b - 140) * 32 + w;
            for (int row = ws; row < G_DIM; row += 224) {
                const float4* wr = reinterpret_cast<const float4*>(Whh + (size_t)row * P_DIM);
                float acc = 0.f;
#pragma unroll
                for (int j = 0; j < 4; j++) {
                    float4 wv = wr[lane + 32 * j];
                    float4 xv = __ldg(s4 + lane + 32 * j);
                    acc += wv.x * xv.x + wv.y * xv.y + wv.z * xv.z + wv.w * xv.w;
                }
                acc = warp_sum(acc);
                if (lane == 0) g_gh[row] = acc + bhh[row];
            }
        } else {
            // mem copy (63 non-slot rows) + sumsq zero
            int slot = wptr[0] & (N_SLOTS - 1);
#pragma unroll 4
            for (int k = 0; k < 32; k++) {
                int idx = t + k * 1024;                    // float4 idx 0..32767
                int row = idx >> 9;
                if (row != slot) {
                    float4 v = __ldg(mem4 + idx);
                    float* d = out + OFF_MEM + (size_t)idx * 4;
                    d[0] = v.x; d[1] = v.y; d[2] = v.z; d[3] = v.w;
                }
            }
            if (t == 0) g_sumsq = 0.f;
        }
    }

    grid_bar(1);

    // ===================== Phase B: finalize columns ========================
    if (b < 128) {
        // block b owns float4 columns [b*4, b*4+4); 148 partials each.
        int g = t >> 7;       // 0..7 (0..3 active)
        int p = t & 127;
        int col = b * 4 + g;
        float4 s = make_float4(0.f,0.f,0.f,0.f);
        if (g < 4) {
            s = g_part[p * H4 + col];
            if (p < GRID - 128) {
                float4 e = g_part[(128 + p) * H4 + col];
                s.x += e.x; s.y += e.y; s.z += e.z; s.w += e.w;
            }
        }
#pragma unroll
        for (int o = 16; o > 0; o >>= 1) {
            s.x += __shfl_xor_sync(0xFFFFFFFFu, s.x, o);
            s.y += __shfl_xor_sync(0xFFFFFFFFu, s.y, o);
            s.z += __shfl_xor_sync(0xFFFFFFFFu, s.z, o);
            s.w += __shfl_xor_sync(0xFFFFFFFFu, s.w, o);
        }
        if (g < 4 && lane == 0) sfin[g * 4 + ((t >> 5) & 3)] = s;
        __syncthreads();
        if (g < 4 && p == 0) {
            float4 a = make_float4(0.f,0.f,0.f,0.f);
#pragma unroll
            for (int i = 0; i < 4; i++) {
                float4 v = sfin[g * 4 + i];
                a.x += v.x; a.y += v.y; a.z += v.z; a.w += v.w;
            }
            const float inv = 1.0f / (float)R_ROWS;
            a.x *= inv; a.y *= inv; a.z *= inv; a.w *= inv;
            reinterpret_cast<float4*>(g_actual)[col] = a;
            float4 pd = reinterpret_cast<const float4*>(g_predicted)[col];
            float ex = a.x - pd.x, ey = a.y - pd.y, ez = a.z - pd.z, ew = a.w - pd.w;
            float* eo = out + OFF_ERR + col * 4;
            eo[0] = ex; eo[1] = ey; eo[2] = ez; eo[3] = ew;
            atomicAdd(&g_sumsq, ex * ex + ey * ey + ez * ez + ew * ew);
        }
    }

    grid_bar(2);

    // ===================== Phase C: x_gru + surprise-dependent outs =========
    if (t < H4) shv[t] = reinterpret_cast<const float4*>(g_actual)[t];
    __syncthreads();
    {
        int r = w * GRID + b;        // spread rows across ALL 148 blocks
        if (r < H_DIM) {
            const float4* wr = reinterpret_cast<const float4*>(ipw + (size_t)r * H_DIM);
            float acc = 0.f;
#pragma unroll
            for (int j = 0; j < 16; j++) {
                float4 wv = wr[lane + 32 * j];
                float4 xv = shv[lane + 32 * j];
                acc += wv.x * xv.x + wv.y * xv.y + wv.z * xv.z + wv.w * xv.w;
            }
            acc = warp_sum(acc);
            if (lane == 0) g_xgru[r] = acc;
        } else if (w == 14 && b < 35) {
            // surprise-dependent small outputs (warp 14: r = 2072+b >= 2048, row-free)
            float sp = sigmoidf_(scale[0] * sqrtf(g_sumsq) * rsqrtf((float)H_DIM));
            int slot = wptr[0] & (N_SLOTS - 1);
            if (b < 32) {
                int i = b * 64 + lane * 2;     // slot row: 32 warps x 64 floats
                float2 a = *reinterpret_cast<const float2*>(g_actual + i);
                float* d = out + OFF_MEM + (size_t)slot * H_DIM + i;
                d[0] = a.x * sp; d[1] = a.y * sp;
            } else if (b < 34) {
                int i = (b - 32) * 32 + lane;  // strength 0..63
                float dec = (float)exp(8192.0 * log(0.999));
                out[OFF_STR + i] = (i == slot) ? sp : strength[i] * dec;
            } else if (lane == 0) {
                out[OFF_SURPRISE] = sp;
            }
        }
    }

    grid_bar(3);

    // ===================== Phase D: gi = W_ih @ x_gru + b_ih ================
    if (t < H4) shv[t] = reinterpret_cast<const float4*>(g_xgru)[t];
    __syncthreads();
    {
        int r = w * GRID + b;
        if (r < G_DIM) {
            const float4* wr = reinterpret_cast<const float4*>(Wih + (size_t)r * H_DIM);
            float acc = 0.f;
#pragma unroll
            for (int j = 0; j < 16; j++) {
                float4 wv = wr[lane + 32 * j];
                float4 xv = shv[lane + 32 * j];
                acc += wv.x * xv.x + wv.y * xv.y + wv.z * xv.z + wv.w * xv.w;
            }
            acc = warp_sum(acc);
            if (lane == 0) g_gi[r] = acc + bih[r];
        }
    }

    // ===================== Phase E: last-arriving block does GRU combine ====
    __syncthreads();
    if (t == 0) {
        __threadfence();
        s_last = (atomicAdd(&g_count, 1u) == GRID - 1);
    }
    __syncthreads();
    if (s_last) {
        if (t == 0) {
            atomicExch(&g_count, 0u);    // reset barrier state for next replay
            atomicExch(&g_release, 0u);
        }
        if (t < P_DIM) {
            float r = sigmoidf_(__ldcg(&g_gi[t])             + g_gh[t]);
            float z = sigmoidf_(__ldcg(&g_gi[P_DIM + t])     + g_gh[P_DIM + t]);
            float n = tanhf(__ldcg(&g_gi[2 * P_DIM + t]) + r * g_gh[2 * P_DIM + t]);
            out[OFF_PSTATE + t] = (1.0f - z) * n + z * pstate[t];
        }
    }
}

extern "C" void kernel_launch(void* const* d_in, const int* in_sizes, int n_in,
                              void* d_out, int out_size) {
    const float* hidden     = (const float*)d_in[0];
    const float* pred_state = (const float*)d_in[1];
    const float* mem_states = (const float*)d_in[2];
    const float* mem_str    = (const float*)d_in[3];
    const float* W_ih       = (const float*)d_in[4];
    const float* W_hh       = (const float*)d_in[5];
    const float* b_ih       = (const float*)d_in[6];
    const float* b_hh       = (const float*)d_in[7];
    const float* pp_w       = (const float*)d_in[8];
    const float* ip_w       = (const float*)d_in[9];
    const float* s_scale    = (const float*)d_in[10];
    const int*   write_ptr  = (const int*)d_in[11];
    float* out = (float*)d_out;

    k_fused<<<GRID, TPB>>>((const float4*)hidden, pred_state,
                           (const float4*)mem_states, mem_str,
                           W_ih, W_hh, b_ih, b_hh, pp_w, ip_w,
                           s_scale, write_ptr, out);
}

// round 9
// speedup vs baseline: 1.6702x; 1.6702x over previous
#include <cuda_runtime.h>
#include <math.h>

// Shapes: B=2, S=8192 -> R=16384 rows; H=2048 (=512 float4); P=512; 3P=1536; 64 slots
#define GRID     148
#define TPB      1024
#define R_ROWS   16384
#define H_DIM    2048
#define H4       512
#define P_DIM    512
#define G_DIM    1536
#define N_SLOTS  64

// Output layout (fp32, concatenated)
#define OFF_SURPRISE 0
#define OFF_ERR      1
#define OFF_PRED     2049
#define OFF_MEM      4097
#define OFF_STR      135169
#define OFF_PSTATE   135233

// Device scratch
__device__ __align__(16) float4 g_part[128 * H4];   // per-block reduce partials (1MB)
__device__ __align__(16) float  g_actual[H_DIM];
__device__ __align__(16) float  g_predicted[H_DIM];
__device__ __align__(16) float  g_xgru[H_DIM];
__device__ __align__(16) float  g_gi[G_DIM];
__device__ __align__(16) float  g_gh[G_DIM];
__device__ float    g_sumsq;
__device__ unsigned g_count   = 0;   // barrier arrivals (self-resetting)
__device__ unsigned g_release = 0;   // barrier release flag; toggles 1,0,1,0 -> ends 0

__device__ __forceinline__ float warp_sum(float v) {
#pragma unroll
    for (int o = 16; o > 0; o >>= 1) v += __shfl_xor_sync(0xFFFFFFFFu, v, o);
    return v;
}
__device__ __forceinline__ float sigmoidf_(float x) { return 1.0f / (1.0f + expf(-x)); }

// Grid-wide barrier (toggle release 1,0,1,0 -> ends 0, replay-safe).
// All 148 blocks co-resident (1 block/SM via __launch_bounds__(1024,1)).
__device__ __forceinline__ void grid_bar(unsigned expect) {
    __syncthreads();
    if (threadIdx.x == 0) {
        __threadfence();
        unsigned t = atomicAdd(&g_count, 1u);
        if (t == GRID - 1) {
            atomicExch(&g_count, 0u);
            __threadfence();
            atomicExch(&g_release, expect);
        } else {
            while (*(volatile unsigned*)&g_release != expect) __nanosleep(64);
        }
        __threadfence();
    }
    __syncthreads();
}

__global__ void __launch_bounds__(TPB, 1)
k_fused(const float4* __restrict__ hs,       // hidden_states (16384 x 512 float4)
        const float*  __restrict__ pstate,   // (512,)
        const float4* __restrict__ mem4,     // mem_states (64 x 512 float4)
        const float*  __restrict__ strength, // (64,)
        const float*  __restrict__ Wih,      // (1536,2048)
        const float*  __restrict__ Whh,      // (1536,512)
        const float*  __restrict__ bih,
        const float*  __restrict__ bhh,
        const float*  __restrict__ ppw,      // (2048,512)
        const float*  __restrict__ ipw,      // (2048,2048)
        const float*  __restrict__ scale,
        const int*    __restrict__ wptr,
        float* __restrict__ out) {
    __shared__ float4 shv[H4];      // 8KB staging
    __shared__ float4 sfin[16];

    const int b = blockIdx.x, t = threadIdx.x;
    const int lane = t & 31, w = t >> 5;

    // ===================== Phase A (identical to R4) ========================
    if (b < 128) {
        // Big reduction: block b sums rows [b*128, b*128+128) into g_part[b].
        const int c = t & 511;            // float4 column
        const int half = t >> 9;          // 0/1: which 64-row half
        size_t base = (size_t)(b * 128 + half * 64) * H4 + c;
        float4 a0 = make_float4(0.f,0.f,0.f,0.f), a1 = a0;
#pragma unroll 8
        for (int k = 0; k < 64; k += 2) {
            float4 v0 = __ldcs(hs + base + (size_t)k * H4);
            float4 v1 = __ldcs(hs + base + (size_t)(k + 1) * H4);
            a0.x += v0.x; a0.y += v0.y; a0.z += v0.z; a0.w += v0.w;
            a1.x += v1.x; a1.y += v1.y; a1.z += v1.z; a1.w += v1.w;
        }
        float4 a; a.x = a0.x + a1.x; a.y = a0.y + a1.y; a.z = a0.z + a1.z; a.w = a0.w + a1.w;
        if (half) shv[c] = a;
        __syncthreads();
        if (!half) {
            float4 o = shv[c];
            a.x += o.x; a.y += o.y; a.z += o.z; a.w += o.w;
            g_part[b * H4 + c] = a;
        }
    } else if (b < 138) {
        // predicted = pred_proj_w @ pred_state (2048 rows, K=512), warp-per-row
        int ws = (b - 128) * 32 + w;                       // 0..319
        const float4* s4 = reinterpret_cast<const float4*>(pstate);
        for (int row = ws; row < H_DIM; row += 320) {
            const float4* wr = reinterpret_cast<const float4*>(ppw + (size_t)row * P_DIM);
            float acc = 0.f;
#pragma unroll
            for (int j = 0; j < 4; j++) {
                float4 wv = wr[lane + 32 * j];
                float4 xv = __ldg(s4 + lane + 32 * j);
                acc += wv.x * xv.x + wv.y * xv.y + wv.z * xv.z + wv.w * xv.w;
            }
            acc = warp_sum(acc);
            if (lane == 0) { g_predicted[row] = acc; out[OFF_PRED + row] = acc; }
        }
    } else if (b < 146) {
        // gh = W_hh @ pred_state + b_hh (1536 rows, K=512), warp-per-row
        int ws = (b - 138) * 32 + w;                       // 0..255
        const float4* s4 = reinterpret_cast<const float4*>(pstate);
        for (int row = ws; row < G_DIM; row += 256) {
            const float4* wr = reinterpret_cast<const float4*>(Whh + (size_t)row * P_DIM);
            float acc = 0.f;
#pragma unroll
            for (int j = 0; j < 4; j++) {
                float4 wv = wr[lane + 32 * j];
                float4 xv = __ldg(s4 + lane + 32 * j);
                acc += wv.x * xv.x + wv.y * xv.y + wv.z * xv.z + wv.w * xv.w;
            }
            acc = warp_sum(acc);
            if (lane == 0) g_gh[row] = acc + bhh[row];
        }
    } else {
        // mem copy (63 non-slot rows) + sumsq zero
        int gid = (b - 146) * TPB + t;                     // 0..2047
        int slot = wptr[0] & (N_SLOTS - 1);
#pragma unroll
        for (int k = 0; k < 16; k++) {
            int idx = gid + k * 2048;                      // float4 idx 0..32767
            int row = idx >> 9;
            if (row != slot) {
                float4 v = __ldg(mem4 + idx);
                float* d = out + OFF_MEM + (size_t)idx * 4;
                d[0] = v.x; d[1] = v.y; d[2] = v.z; d[3] = v.w;
            }
        }
        if (b == 147 && t == 0) g_sumsq = 0.f;
    }

    grid_bar(1);

    // ===================== Phase B: finalize columns (identical to R4) ======
    if (b < 128) {
        int g = t >> 7;       // 0..7 (only 0..3 active)
        int p = t & 127;
        float4 s = make_float4(0.f,0.f,0.f,0.f);
        int col = b * 4 + g;
        if (g < 4) s = g_part[p * H4 + col];
#pragma unroll
        for (int o = 16; o > 0; o >>= 1) {
            s.x += __shfl_xor_sync(0xFFFFFFFFu, s.x, o);
            s.y += __shfl_xor_sync(0xFFFFFFFFu, s.y, o);
            s.z += __shfl_xor_sync(0xFFFFFFFFu, s.z, o);
            s.w += __shfl_xor_sync(0xFFFFFFFFu, s.w, o);
        }
        if (g < 4 && lane == 0) sfin[g * 4 + ((t >> 5) & 3)] = s;
        __syncthreads();
        if (g < 4 && p == 0) {
            float4 a = make_float4(0.f,0.f,0.f,0.f);
#pragma unroll
            for (int i = 0; i < 4; i++) {
                float4 v = sfin[g * 4 + i];
                a.x += v.x; a.y += v.y; a.z += v.z; a.w += v.w;
            }
            const float inv = 1.0f / (float)R_ROWS;
            a.x *= inv; a.y *= inv; a.z *= inv; a.w *= inv;
            reinterpret_cast<float4*>(g_actual)[col] = a;
            float4 pd = reinterpret_cast<const float4*>(g_predicted)[col];
            float ex = a.x - pd.x, ey = a.y - pd.y, ez = a.z - pd.z, ew = a.w - pd.w;
            float* eo = out + OFF_ERR + col * 4;
            eo[0] = ex; eo[1] = ey; eo[2] = ez; eo[3] = ew;
            atomicAdd(&g_sumsq, ex * ex + ey * ey + ez * ez + ew * ew);
        }
    }

    grid_bar(0);

    // ======= Phase C: x_gru spread over ALL blocks (THE one change) ========
    if (t < H4) shv[t] = reinterpret_cast<const float4*>(g_actual)[t];
    __syncthreads();
    {
        int r = b * 14 + w;              // block-contiguous: 14 rows per block
        if (w < 14 && r < H_DIM) {
            const float4* wr = reinterpret_cast<const float4*>(ipw + (size_t)r * H_DIM);
            float acc = 0.f;
#pragma unroll
            for (int j = 0; j < 16; j++) {
                float4 wv = wr[lane + 32 * j];
                float4 xv = shv[lane + 32 * j];
                acc += wv.x * xv.x + wv.y * xv.y + wv.z * xv.z + wv.w * xv.w;
            }
            acc = warp_sum(acc);
            if (lane == 0) g_xgru[r] = acc;
        } else if (w == 15 && b < 35) {
            // surprise-dependent small outputs (warp 15 never carries a row)
            float sp = sigmoidf_(scale[0] * sqrtf(g_sumsq) * rsqrtf((float)H_DIM));
            int slot = wptr[0] & (N_SLOTS - 1);
            if (b < 32) {
                int i = b * 64 + lane * 2;     // slot row: 32 warps x 64 floats
                float2 a = *reinterpret_cast<const float2*>(g_actual + i);
                float* d = out + OFF_MEM + (size_t)slot * H_DIM + i;
                d[0] = a.x * sp; d[1] = a.y * sp;
            } else if (b < 34) {
                int i = (b - 32) * 32 + lane;  // strength 0..63
                float dec = (float)exp(8192.0 * log(0.999));
                out[OFF_STR + i] = (i == slot) ? sp : strength[i] * dec;
            } else if (lane == 0) {
                out[OFF_SURPRISE] = sp;
            }
        }
    }

    grid_bar(1);

    // ======= Phase D: gi spread over ALL blocks (same change) ===============
    if (t < H4) shv[t] = reinterpret_cast<const float4*>(g_xgru)[t];
    __syncthreads();
    {
        int r = b * 11 + w;              // 11 rows per block
        if (w < 11 && r < G_DIM) {
            const float4* wr = reinterpret_cast<const float4*>(Wih + (size_t)r * H_DIM);
            float acc = 0.f;
#pragma unroll
            for (int j = 0; j < 16; j++) {
                float4 wv = wr[lane + 32 * j];
                float4 xv = shv[lane + 32 * j];
                acc += wv.x * xv.x + wv.y * xv.y + wv.z * xv.z + wv.w * xv.w;
            }
            acc = warp_sum(acc);
            if (lane == 0) g_gi[r] = acc + bih[r];
        }
    }

    grid_bar(0);

    // ===================== Phase E: GRU combine (block 0, as R4) ============
    if (b == 0 && t < P_DIM) {
        float r = sigmoidf_(g_gi[t]             + g_gh[t]);
        float z = sigmoidf_(g_gi[P_DIM + t]     + g_gh[P_DIM + t]);
        float n = tanhf(g_gi[2 * P_DIM + t] + r * g_gh[2 * P_DIM + t]);
        out[OFF_PSTATE + t] = (1.0f - z) * n + z * pstate[t];
    }
}

extern "C" void kernel_launch(void* const* d_in, const int* in_sizes, int n_in,
                              void* d_out, int out_size) {
    const float* hidden     = (const float*)d_in[0];
    const float* pred_state = (const float*)d_in[1];
    const float* mem_states = (const float*)d_in[2];
    const float* mem_str    = (const float*)d_in[3];
    const float* W_ih       = (const float*)d_in[4];
    const float* W_hh       = (const float*)d_in[5];
    const float* b_ih       = (const float*)d_in[6];
    const float* b_hh       = (const float*)d_in[7];
    const float* pp_w       = (const float*)d_in[8];
    const float* ip_w       = (const float*)d_in[9];
    const float* s_scale    = (const float*)d_in[10];
    const int*   write_ptr  = (const int*)d_in[11];
    float* out = (float*)d_out;

    k_fused<<<GRID, TPB>>>((const float4*)hidden, pred_state,
                           (const float4*)mem_states, mem_str,
                           W_ih, W_hh, b_ih, b_hh, pp_w, ip_w,
                           s_scale, write_ptr, out);
}